// round 15
// baseline (speedup 1.0000x reference)
#include <cuda_runtime.h>
#include <cuda_fp16.h>

// Trilinear 3D grid sample, (y,z,c)-fused fp16 corner layout.
// im:      [B, X, Y, Z, C] float32, B=2, X=Y=Z=160, C=2
// defgrid: [B, X, Y, Z, 3] float32
// out:     [B, X, Y, Z, C] float32
//
// P2[b][x][y][z] = 8 halves (16B): {(y,z),(y,z+1),(y+1,z),(y+1,z+1)} x {c0,c1}.
// Gather (best-known config, do not touch): 2 voxels/thread, 2 divergent
// 16B table loads per voxel, .cs streaming for coords/out, 32 regs.
// Preprocess: 4 consecutive-z voxels per thread (amortized loads, more ILP).
// Sequential schedule: pre(0) -> gather(0) -> pre(1) -> gather(1).

#define XD 160
#define YD 160
#define ZD 160
#define BD 2
#define VOL (XD * YD * ZD)          // 4,096,000
#define THREADS 256
#define PRE_BLOCKS (VOL / 4 / THREADS)      // 4000 (4 voxels/thread)
#define GATHER_BLOCKS (VOL / 2 / THREADS)   // 8000 (2 voxels/thread)

__device__ uint4 g_P2[BD][VOL];

__device__ __forceinline__ unsigned int pack_h2(float a, float b) {
    __half2 h = __floats2half2_rn(a, b);
    return *(unsigned int*)&h;
}

// ---------- preprocess: 4 consecutive-z voxels per thread ----------
// Thread t covers entries i..i+3 with i = 4t; ZD=160 % 4 == 0 so the quad
// stays inside one z-row. Needs voxels z..z+4 (clamped) from rows y, y+1.
__global__ __launch_bounds__(THREADS) void preprocess_kernel(
    const float2* __restrict__ im, int b)
{
    int t = blockIdx.x * THREADS + threadIdx.x;
    if (t >= VOL / 4) return;

    int i = t * 4;              // multiple of 4
    int z = i % ZD;             // 0,4,...,156
    int y = (i / ZD) % YD;

    const float2* __restrict__ imb = im + (size_t)b * VOL;
    int yp = (y < YD - 1) ? ZD : 0;   // clamp y+1
    int j  = i + yp;

    // row y: voxels z..z+3 (two aligned float4s) + voxel z+4 (clamped)
    float4 a0 = __ldcs((const float4*)(imb + i));        // z, z+1
    float4 a1 = __ldcs((const float4*)(imb + i + 2));    // z+2, z+3
    float2 a2 = (z + 4 < ZD) ? __ldcs(&imb[i + 4])       // z+4
                             : make_float2(a1.z, a1.w);  // clamp -> z+3
    // row y+1
    float4 b0 = __ldcs((const float4*)(imb + j));
    float4 b1 = __ldcs((const float4*)(imb + j + 2));
    float2 b2 = (z + 4 < ZD) ? __ldcs(&imb[j + 4])
                             : make_float2(b1.z, b1.w);

    // pack row-y voxels z..z+4 and row-(y+1) voxels z..z+4 as half2
    unsigned int ya_[5], yb_[5];
    ya_[0] = pack_h2(a0.x, a0.y);
    ya_[1] = pack_h2(a0.z, a0.w);
    ya_[2] = pack_h2(a1.x, a1.y);
    ya_[3] = pack_h2(a1.z, a1.w);
    ya_[4] = pack_h2(a2.x, a2.y);
    yb_[0] = pack_h2(b0.x, b0.y);
    yb_[1] = pack_h2(b0.z, b0.w);
    yb_[2] = pack_h2(b1.x, b1.y);
    yb_[3] = pack_h2(b1.z, b1.w);
    yb_[4] = pack_h2(b2.x, b2.y);

#pragma unroll
    for (int k = 0; k < 4; k++) {
        uint4 p;
        p.x = ya_[k];       // (y  , z+k  )
        p.y = ya_[k + 1];   // (y  , z+k+1)
        p.z = yb_[k];       // (y+1, z+k  )
        p.w = yb_[k + 1];   // (y+1, z+k+1)
        g_P2[b][i + k] = p;
    }
}

__device__ __forceinline__ float2 h2f(unsigned int u) {
    __half2 h = *(__half2*)&u;
    return __half22float2(h);
}

__device__ __forceinline__ float2 interp_voxel(
    float x, float y, float z, uint4 q0, uint4 q1,
    int x0, int y0u, int z0u, int zc)
{
    // Lower-edge clip duplication (coords >= 0 so ~never taken; keeps exact
    // reference semantics).
    if (z0u < 0) { q0.y = q0.x; q0.w = q0.z; q1.y = q1.x; q1.w = q1.z; }
    if (y0u < 0) { q0.z = q0.x; q0.w = q0.y; q1.z = q1.x; q1.w = q1.y; }

    float2 Ia = h2f(q0.x), Ib = h2f(q0.y), Ic = h2f(q0.z), Id = h2f(q0.w);
    float2 Ie = h2f(q1.x), If = h2f(q1.y), Ig = h2f(q1.z), Ih = h2f(q1.w);

    int y0 = min(max(y0u, 0), YD - 1);
    const float xd = x - (float)x0;
    const float yd = y - (float)y0;
    const float zd = z - (float)zc;
    const float xm = 1.0f - xd;
    const float ym = 1.0f - yd;
    const float zm = 1.0f - zd;

    float cae0 = Ia.x * xm + Ie.x * xd;
    float cae1 = Ia.y * xm + Ie.y * xd;
    float cbf0 = Ib.x * xm + If.x * xd;
    float cbf1 = Ib.y * xm + If.y * xd;
    float ccg0 = Ic.x * xm + Ig.x * xd;
    float ccg1 = Ic.y * xm + Ig.y * xd;
    float cdh0 = Id.x * xm + Ih.x * xd;
    float cdh1 = Id.y * xm + Ih.y * xd;

    float c0_0 = cae0 * ym + ccg0 * yd;
    float c0_1 = cae1 * ym + ccg1 * yd;
    float c1_0 = cbf0 * ym + cdh0 * yd;
    float c1_1 = cbf1 * ym + cdh1 * yd;

    float2 r;
    r.x = c0_0 * zm + c1_0 * zd;
    r.y = c0_1 * zm + c1_1 * zd;
    return r;
}

// ---------- gather: one voxel-pair per thread (best-known config) ----------
__global__ __launch_bounds__(THREADS) void gather_kernel(
    const float* __restrict__ defgrid,
    float4* __restrict__ out, int b)
{
    int t = blockIdx.x * THREADS + threadIdx.x;
    if (t >= VOL / 2) return;

    int i  = t * 2;
    int gi = b * VOL + i;

    const float2* dg = (const float2*)(defgrid + (size_t)3 * gi);
    float2 d0 = __ldcs(dg + 0);   // xA, yA
    float2 d1 = __ldcs(dg + 1);   // zA, xB
    float2 d2 = __ldcs(dg + 2);   // yB, zB

    const float xA = d0.x, yA = d0.y, zA = d1.x;
    const float xB = d1.y, yB = d2.x, zB = d2.y;

    int xA0u = (int)floorf(xA), yA0u = (int)floorf(yA), zA0u = (int)floorf(zA);
    int xA0 = min(max(xA0u, 0), XD - 1);
    int xA1 = min(max(xA0u + 1, 0), XD - 1);
    int yA0 = min(max(yA0u, 0), YD - 1);
    int zAc = min(max(zA0u, 0), ZD - 1);

    int xB0u = (int)floorf(xB), yB0u = (int)floorf(yB), zB0u = (int)floorf(zB);
    int xB0 = min(max(xB0u, 0), XD - 1);
    int xB1 = min(max(xB0u + 1, 0), XD - 1);
    int yB0 = min(max(yB0u, 0), YD - 1);
    int zBc = min(max(zB0u, 0), ZD - 1);

    const uint4* __restrict__ Pb = g_P2[b];

    uint4 qA0 = Pb[(xA0 * YD + yA0) * ZD + zAc];
    uint4 qA1 = Pb[(xA1 * YD + yA0) * ZD + zAc];
    uint4 qB0 = Pb[(xB0 * YD + yB0) * ZD + zBc];
    uint4 qB1 = Pb[(xB1 * YD + yB0) * ZD + zBc];

    float2 rA = interp_voxel(xA, yA, zA, qA0, qA1, xA0, yA0u, zA0u, zAc);
    float2 rB = interp_voxel(xB, yB, zB, qB0, qB1, xB0, yB0u, zB0u, zBc);

    float4 o = make_float4(rA.x, rA.y, rB.x, rB.y);
    __stcs(&out[gi / 2], o);
}

extern "C" void kernel_launch(void* const* d_in, const int* in_sizes, int n_in,
                              void* d_out, int out_size)
{
    const float2* im     = (const float2*)d_in[0];
    const float* defgrid = (const float*)d_in[1];
    float4* out          = (float4*)d_out;

    for (int b = 0; b < BD; b++) {
        preprocess_kernel<<<PRE_BLOCKS, THREADS>>>(im, b);
        gather_kernel<<<GATHER_BLOCKS, THREADS>>>(defgrid, out, b);
    }
}

// round 16
// speedup vs baseline: 1.0841x; 1.0841x over previous
#include <cuda_runtime.h>
#include <cuda_fp16.h>

// Trilinear 3D grid sample, (y,z,c)-fused fp16 corner layout.
// im:      [B, X, Y, Z, C] float32, B=2, X=Y=Z=160, C=2
// defgrid: [B, X, Y, Z, 3] float32
// out:     [B, X, Y, Z, C] float32
//
// P2[b][x][y][z] = 8 halves (16B): {(y,z),(y,z+1),(y+1,z),(y+1,z+1)} x {c0,c1}.
// Preprocess: 1 voxel/thread (contiguous 16B stores = 4 wf/instr; best).
// Gather: 2 voxels/thread, 2 divergent 16B table loads per voxel;
//   coords staged block-wide through smem with dense float4 loads
//   (0.1 wf/voxel vs 0.56 for direct strided loads).
// Sequential schedule: pre(0) -> gather(0) -> pre(1) -> gather(1).

#define XD 160
#define YD 160
#define ZD 160
#define BD 2
#define VOL (XD * YD * ZD)          // 4,096,000
#define THREADS 256
#define PRE_BLOCKS (VOL / THREADS)          // 16000 (1 voxel/thread)
#define GATHER_BLOCKS (VOL / 2 / THREADS)   // 8000 (2 voxels/thread)
#define COORD_BYTES (THREADS * 24)          // 6144B of coords per block
#define COORD_F4 (COORD_BYTES / 16)         // 384 float4 loads per block

__device__ uint4 g_P2[BD][VOL];

// ---------- preprocess: 1 voxel per thread (R4 config) ----------
__global__ __launch_bounds__(THREADS) void preprocess_kernel(
    const float2* __restrict__ im, int b)
{
    int i = blockIdx.x * THREADS + threadIdx.x;
    if (i >= VOL) return;

    int z = i % ZD;
    int y = (i / ZD) % YD;

    const float2* __restrict__ imb = im + (size_t)b * VOL;
    int zp = (z < ZD - 1) ? 1 : 0;    // clamp z+1
    int yp = (y < YD - 1) ? ZD : 0;   // clamp y+1

    float2 v00 = __ldcs(&imb[i]);
    float2 v01 = __ldcs(&imb[i + zp]);
    float2 v10 = __ldcs(&imb[i + yp]);
    float2 v11 = __ldcs(&imb[i + yp + zp]);

    __half2 h00 = __float22half2_rn(v00);
    __half2 h01 = __float22half2_rn(v01);
    __half2 h10 = __float22half2_rn(v10);
    __half2 h11 = __float22half2_rn(v11);

    uint4 pk;
    pk.x = *(unsigned int*)&h00;
    pk.y = *(unsigned int*)&h01;
    pk.z = *(unsigned int*)&h10;
    pk.w = *(unsigned int*)&h11;
    g_P2[b][i] = pk;
}

__device__ __forceinline__ float2 h2f(unsigned int u) {
    __half2 h = *(__half2*)&u;
    return __half22float2(h);
}

__device__ __forceinline__ float2 interp_voxel(
    float x, float y, float z, uint4 q0, uint4 q1,
    int x0, int y0u, int z0u, int zc)
{
    // Lower-edge clip duplication (coords >= 0 so ~never taken; keeps exact
    // reference semantics).
    if (z0u < 0) { q0.y = q0.x; q0.w = q0.z; q1.y = q1.x; q1.w = q1.z; }
    if (y0u < 0) { q0.z = q0.x; q0.w = q0.y; q1.z = q1.x; q1.w = q1.y; }

    float2 Ia = h2f(q0.x), Ib = h2f(q0.y), Ic = h2f(q0.z), Id = h2f(q0.w);
    float2 Ie = h2f(q1.x), If = h2f(q1.y), Ig = h2f(q1.z), Ih = h2f(q1.w);

    int y0 = min(max(y0u, 0), YD - 1);
    const float xd = x - (float)x0;
    const float yd = y - (float)y0;
    const float zd = z - (float)zc;
    const float xm = 1.0f - xd;
    const float ym = 1.0f - yd;
    const float zm = 1.0f - zd;

    float cae0 = Ia.x * xm + Ie.x * xd;
    float cae1 = Ia.y * xm + Ie.y * xd;
    float cbf0 = Ib.x * xm + If.x * xd;
    float cbf1 = Ib.y * xm + If.y * xd;
    float ccg0 = Ic.x * xm + Ig.x * xd;
    float ccg1 = Ic.y * xm + Ig.y * xd;
    float cdh0 = Id.x * xm + Ih.x * xd;
    float cdh1 = Id.y * xm + Ih.y * xd;

    float c0_0 = cae0 * ym + ccg0 * yd;
    float c0_1 = cae1 * ym + ccg1 * yd;
    float c1_0 = cbf0 * ym + cdh0 * yd;
    float c1_1 = cbf1 * ym + cdh1 * yd;

    float2 r;
    r.x = c0_0 * zm + c1_0 * zd;
    r.y = c0_1 * zm + c1_1 * zd;
    return r;
}

// ---------- gather: smem-staged coords, one voxel-pair per thread ----------
__global__ __launch_bounds__(THREADS) void gather_kernel(
    const float* __restrict__ defgrid,
    float4* __restrict__ out, int b)
{
    __shared__ float4 s_coord[COORD_F4];   // 6144B: coords for 512 voxels

    int tid = threadIdx.x;

    // Dense stage: block's defgrid slice (exactly COORD_BYTES, no tail —
    // VOL*12 is divisible by COORD_BYTES since VOL = 8000*512).
    {
        const float4* src = (const float4*)
            (defgrid + (size_t)b * VOL * 3 + (size_t)blockIdx.x * (COORD_BYTES / 4));
        s_coord[tid] = __ldcs(&src[tid]);                       // 0..255
        if (tid < COORD_F4 - THREADS)
            s_coord[tid + THREADS] = __ldcs(&src[tid + THREADS]); // 256..383
    }
    __syncthreads();

    // This thread's voxel-pair coords: 24B at smem offset tid*24.
    const float2* sm2 = (const float2*)s_coord;
    float2 d0 = sm2[3 * tid + 0];   // xA, yA
    float2 d1 = sm2[3 * tid + 1];   // zA, xB
    float2 d2 = sm2[3 * tid + 2];   // yB, zB

    int t  = blockIdx.x * THREADS + tid;
    int i  = t * 2;
    int gi = b * VOL + i;

    const float xA = d0.x, yA = d0.y, zA = d1.x;
    const float xB = d1.y, yB = d2.x, zB = d2.y;

    int xA0u = (int)floorf(xA), yA0u = (int)floorf(yA), zA0u = (int)floorf(zA);
    int xA0 = min(max(xA0u, 0), XD - 1);
    int xA1 = min(max(xA0u + 1, 0), XD - 1);
    int yA0 = min(max(yA0u, 0), YD - 1);
    int zAc = min(max(zA0u, 0), ZD - 1);

    int xB0u = (int)floorf(xB), yB0u = (int)floorf(yB), zB0u = (int)floorf(zB);
    int xB0 = min(max(xB0u, 0), XD - 1);
    int xB1 = min(max(xB0u + 1, 0), XD - 1);
    int yB0 = min(max(yB0u, 0), YD - 1);
    int zBc = min(max(zB0u, 0), ZD - 1);

    const uint4* __restrict__ Pb = g_P2[b];

    uint4 qA0 = Pb[(xA0 * YD + yA0) * ZD + zAc];
    uint4 qA1 = Pb[(xA1 * YD + yA0) * ZD + zAc];
    uint4 qB0 = Pb[(xB0 * YD + yB0) * ZD + zBc];
    uint4 qB1 = Pb[(xB1 * YD + yB0) * ZD + zBc];

    float2 rA = interp_voxel(xA, yA, zA, qA0, qA1, xA0, yA0u, zA0u, zAc);
    float2 rB = interp_voxel(xB, yB, zB, qB0, qB1, xB0, yB0u, zB0u, zBc);

    float4 o = make_float4(rA.x, rA.y, rB.x, rB.y);
    __stcs(&out[gi / 2], o);
}

extern "C" void kernel_launch(void* const* d_in, const int* in_sizes, int n_in,
                              void* d_out, int out_size)
{
    const float2* im     = (const float2*)d_in[0];
    const float* defgrid = (const float*)d_in[1];
    float4* out          = (float4*)d_out;

    for (int b = 0; b < BD; b++) {
        preprocess_kernel<<<PRE_BLOCKS, THREADS>>>(im, b);
        gather_kernel<<<GATHER_BLOCKS, THREADS>>>(defgrid, out, b);
    }
}

// round 17
// speedup vs baseline: 1.1102x; 1.0240x over previous
#include <cuda_runtime.h>
#include <cuda_fp16.h>

// Trilinear 3D grid sample, (y,z,c)-fused fp16 corner layout.
// im:      [B, X, Y, Z, C] float32, B=2, X=Y=Z=160, C=2
// defgrid: [B, X, Y, Z, 3] float32
// out:     [B, X, Y, Z, C] float32
//
// P2[b][x][y][z] = 8 halves (16B): {(y,z),(y,z+1),(y+1,z),(y+1,z+1)} x {c0,c1}.
// Preprocess: 1 voxel/thread, DEFAULT-cached im loads (the 4 neighbor loads
// have ~4x L1 reuse across adjacent threads; .cs was demoting them to L2).
// Gather (proven best config): 2 voxels/thread, 2 divergent 16B table loads
// per voxel, .cs streaming for coords/out, 32 regs, ~88% occupancy.
// Sequential schedule: pre(0) -> gather(0) -> pre(1) -> gather(1).

#define XD 160
#define YD 160
#define ZD 160
#define BD 2
#define VOL (XD * YD * ZD)          // 4,096,000
#define THREADS 256
#define PRE_BLOCKS (VOL / THREADS)          // 16000 (1 voxel/thread)
#define GATHER_BLOCKS (VOL / 2 / THREADS)   // 8000 (2 voxels/thread)

__device__ uint4 g_P2[BD][VOL];

// ---------- preprocess: 1 voxel per thread ----------
__global__ __launch_bounds__(THREADS) void preprocess_kernel(
    const float2* __restrict__ im, int b)
{
    int i = blockIdx.x * THREADS + threadIdx.x;
    if (i >= VOL) return;

    int z = i % ZD;
    int y = (i / ZD) % YD;

    const float2* __restrict__ imb = im + (size_t)b * VOL;
    int zp = (z < ZD - 1) ? 1 : 0;    // clamp z+1
    int yp = (y < YD - 1) ? ZD : 0;   // clamp y+1

    // Default-cached loads: v01/v11 are L1 hits from neighbor threads' lines,
    // and the y+1 row is reused by the next y-group of threads.
    float2 v00 = __ldg(&imb[i]);
    float2 v01 = __ldg(&imb[i + zp]);
    float2 v10 = __ldg(&imb[i + yp]);
    float2 v11 = __ldg(&imb[i + yp + zp]);

    __half2 h00 = __float22half2_rn(v00);
    __half2 h01 = __float22half2_rn(v01);
    __half2 h10 = __float22half2_rn(v10);
    __half2 h11 = __float22half2_rn(v11);

    uint4 pk;
    pk.x = *(unsigned int*)&h00;
    pk.y = *(unsigned int*)&h01;
    pk.z = *(unsigned int*)&h10;
    pk.w = *(unsigned int*)&h11;
    g_P2[b][i] = pk;
}

__device__ __forceinline__ float2 h2f(unsigned int u) {
    __half2 h = *(__half2*)&u;
    return __half22float2(h);
}

__device__ __forceinline__ float2 interp_voxel(
    float x, float y, float z, uint4 q0, uint4 q1,
    int x0, int y0u, int z0u, int zc)
{
    // Lower-edge clip duplication (coords >= 0 so ~never taken; keeps exact
    // reference semantics).
    if (z0u < 0) { q0.y = q0.x; q0.w = q0.z; q1.y = q1.x; q1.w = q1.z; }
    if (y0u < 0) { q0.z = q0.x; q0.w = q0.y; q1.z = q1.x; q1.w = q1.y; }

    float2 Ia = h2f(q0.x), Ib = h2f(q0.y), Ic = h2f(q0.z), Id = h2f(q0.w);
    float2 Ie = h2f(q1.x), If = h2f(q1.y), Ig = h2f(q1.z), Ih = h2f(q1.w);

    int y0 = min(max(y0u, 0), YD - 1);
    const float xd = x - (float)x0;
    const float yd = y - (float)y0;
    const float zd = z - (float)zc;
    const float xm = 1.0f - xd;
    const float ym = 1.0f - yd;
    const float zm = 1.0f - zd;

    float cae0 = Ia.x * xm + Ie.x * xd;
    float cae1 = Ia.y * xm + Ie.y * xd;
    float cbf0 = Ib.x * xm + If.x * xd;
    float cbf1 = Ib.y * xm + If.y * xd;
    float ccg0 = Ic.x * xm + Ig.x * xd;
    float ccg1 = Ic.y * xm + Ig.y * xd;
    float cdh0 = Id.x * xm + Ih.x * xd;
    float cdh1 = Id.y * xm + Ih.y * xd;

    float c0_0 = cae0 * ym + ccg0 * yd;
    float c0_1 = cae1 * ym + ccg1 * yd;
    float c1_0 = cbf0 * ym + cdh0 * yd;
    float c1_1 = cbf1 * ym + cdh1 * yd;

    float2 r;
    r.x = c0_0 * zm + c1_0 * zd;
    r.y = c0_1 * zm + c1_1 * zd;
    return r;
}

// ---------- gather: one voxel-pair per thread (R4 proven config) ----------
__global__ __launch_bounds__(THREADS) void gather_kernel(
    const float* __restrict__ defgrid,
    float4* __restrict__ out, int b)
{
    int t = blockIdx.x * THREADS + threadIdx.x;
    if (t >= VOL / 2) return;

    int i  = t * 2;
    int gi = b * VOL + i;

    const float2* dg = (const float2*)(defgrid + (size_t)3 * gi);
    float2 d0 = __ldcs(dg + 0);   // xA, yA
    float2 d1 = __ldcs(dg + 1);   // zA, xB
    float2 d2 = __ldcs(dg + 2);   // yB, zB

    const float xA = d0.x, yA = d0.y, zA = d1.x;
    const float xB = d1.y, yB = d2.x, zB = d2.y;

    int xA0u = (int)floorf(xA), yA0u = (int)floorf(yA), zA0u = (int)floorf(zA);
    int xA0 = min(max(xA0u, 0), XD - 1);
    int xA1 = min(max(xA0u + 1, 0), XD - 1);
    int yA0 = min(max(yA0u, 0), YD - 1);
    int zAc = min(max(zA0u, 0), ZD - 1);

    int xB0u = (int)floorf(xB), yB0u = (int)floorf(yB), zB0u = (int)floorf(zB);
    int xB0 = min(max(xB0u, 0), XD - 1);
    int xB1 = min(max(xB0u + 1, 0), XD - 1);
    int yB0 = min(max(yB0u, 0), YD - 1);
    int zBc = min(max(zB0u, 0), ZD - 1);

    const uint4* __restrict__ Pb = g_P2[b];

    uint4 qA0 = Pb[(xA0 * YD + yA0) * ZD + zAc];
    uint4 qA1 = Pb[(xA1 * YD + yA0) * ZD + zAc];
    uint4 qB0 = Pb[(xB0 * YD + yB0) * ZD + zBc];
    uint4 qB1 = Pb[(xB1 * YD + yB0) * ZD + zBc];

    float2 rA = interp_voxel(xA, yA, zA, qA0, qA1, xA0, yA0u, zA0u, zAc);
    float2 rB = interp_voxel(xB, yB, zB, qB0, qB1, xB0, yB0u, zB0u, zBc);

    float4 o = make_float4(rA.x, rA.y, rB.x, rB.y);
    __stcs(&out[gi / 2], o);
}

extern "C" void kernel_launch(void* const* d_in, const int* in_sizes, int n_in,
                              void* d_out, int out_size)
{
    const float2* im     = (const float2*)d_in[0];
    const float* defgrid = (const float*)d_in[1];
    float4* out          = (float4*)d_out;

    for (int b = 0; b < BD; b++) {
        preprocess_kernel<<<PRE_BLOCKS, THREADS>>>(im, b);
        gather_kernel<<<GATHER_BLOCKS, THREADS>>>(defgrid, out, b);
    }
}